// round 14
// baseline (speedup 1.0000x reference)
#include <cuda_runtime.h>
#include <cuda_fp16.h>
#include <cstdint>

#define BATCH 256
#define TSEQ  2048
#define DH    512
#define STEPS 2040
#define DIN   384

__device__ float g_hx[(size_t)BATCH * STEPS * DH];

__device__ __forceinline__ unsigned su32(const void* p) {
    return (unsigned)__cvta_generic_to_shared(p);
}
__device__ __forceinline__ void ldsm4(unsigned* r, unsigned a) {
    asm volatile("ldmatrix.sync.aligned.m8n8.x4.shared.b16 {%0,%1,%2,%3}, [%4];"
                 : "=r"(r[0]), "=r"(r[1]), "=r"(r[2]), "=r"(r[3]) : "r"(a));
}
__device__ __forceinline__ void ldsm2(unsigned& r0, unsigned& r1, unsigned a) {
    asm volatile("ldmatrix.sync.aligned.m8n8.x2.shared.b16 {%0,%1}, [%2];"
                 : "=r"(r0), "=r"(r1) : "r"(a));
}
__device__ __forceinline__ void mma16816(float* c, const unsigned* a, unsigned b0, unsigned b1) {
    asm volatile("mma.sync.aligned.m16n8k16.row.col.f32.f16.f16.f32 "
                 "{%0,%1,%2,%3}, {%4,%5,%6,%7}, {%8,%9}, {%0,%1,%2,%3};"
                 : "+f"(c[0]), "+f"(c[1]), "+f"(c[2]), "+f"(c[3])
                 : "r"(a[0]), "r"(a[1]), "r"(a[2]), "r"(a[3]), "r"(b0), "r"(b1));
}
__device__ __forceinline__ float tanh_fast(float v) {
    float r; asm("tanh.approx.f32 %0, %1;" : "=f"(r) : "f"(v)); return r;
}
__device__ __forceinline__ unsigned long long packf2(float a, float b) {
    unsigned long long r;
    asm("mov.b64 %0, {%1,%2};" : "=l"(r) : "f"(a), "f"(b));
    return r;
}
__device__ __forceinline__ void fma2(unsigned long long& acc, unsigned long long a,
                                     unsigned long long b) {
    asm("fma.rn.f32x2 %0, %1, %2, %0;" : "+l"(acc) : "l"(a), "l"(b));
}
__device__ __forceinline__ float2 unpk(unsigned long long v) {
    float2 r;
    asm("mov.b64 {%0,%1}, %2;" : "=f"(r.x), "=f"(r.y) : "l"(v));
    return r;
}

// ===========================================================================
// Phase A: Hx = Xwin[128t x 256k] @ W1x^T, fp16 mma  (R9/R12-passing, verbatim)
// ===========================================================================
#define WS_LD 264
#define CB_LD 132
#define XSP   5408

__global__ void __launch_bounds__(256, 2)
narx_hx(const float* __restrict__ x, const float* __restrict__ W1,
        const float* __restrict__ b1)
{
    extern __shared__ unsigned char smraw[];
    __half* xs = (__half*)smraw;
    __half* ws = (__half*)(smraw + XSP * 2);
    float*  cb = (float*)(smraw + XSP * 2);

    const int tid = threadIdx.x, warp = tid >> 5, lane = tid & 31;
    const int wm = warp & 1, wn = warp >> 1;
    const int t0 = blockIdx.x * 128, J0 = blockIdx.y * 128, b = blockIdx.z;

    {
        const float* xb = x + (size_t)b * (TSEQ * 32) + (size_t)t0 * 32;
        const int lim = TSEQ * 32 - t0 * 32;
        for (int i = tid; i < 4320; i += 256) {
            float v = (i < lim) ? xb[i] : 0.0f;
            xs[(i >> 5) * 40 + (i & 31)] = __float2half_rn(v);
        }
    }
    for (int idx = tid; idx < 128 * 128; idx += 256) {
        int j = idx >> 7, k2 = (idx & 127) << 1;
        const float* w = W1 + (size_t)(J0 + j) * DIN + k2;
        *(__half2*)(ws + j * WS_LD + k2) = __floats2half2_rn(w[0], w[1]);
    }
    __syncthreads();

    float c[4][4][4];
    #pragma unroll
    for (int i = 0; i < 4; i++)
        #pragma unroll
        for (int j = 0; j < 4; j++)
            #pragma unroll
            for (int r = 0; r < 4; r++) c[i][j][r] = 0.0f;

    const unsigned xsb = su32(xs), wsb = su32(ws);
    const int mat = lane >> 3, lrow = lane & 7;

    #pragma unroll 4
    for (int ks = 0; ks < 16; ++ks) {
        unsigned a[4][4], b0[4], b1[4];
        const int col = ks * 16 + (mat >> 1) * 8;
        const int ce  = (col >> 5) * 40 + (col & 31);
        #pragma unroll
        for (int mt = 0; mt < 4; ++mt) {
            int row = wm * 64 + mt * 16 + (mat & 1) * 8 + lrow;
            ldsm4(a[mt], xsb + 2u * (unsigned)(row * 40 + ce));
        }
        const int bcol = ks * 16 + ((lane >> 3) & 1) * 8;
        #pragma unroll
        for (int nt = 0; nt < 4; ++nt) {
            int br = wn * 32 + nt * 8 + lrow;
            ldsm2(b0[nt], b1[nt], wsb + 2u * (unsigned)(br * WS_LD + bcol));
        }
        #pragma unroll
        for (int mt = 0; mt < 4; ++mt)
            #pragma unroll
            for (int nt = 0; nt < 4; ++nt)
                mma16816(c[mt][nt], a[mt], b0[nt], b1[nt]);
    }

    __syncthreads();
    {
        const int g = lane >> 2, tq = lane & 3;
        #pragma unroll
        for (int mt = 0; mt < 4; ++mt)
            #pragma unroll
            for (int nt = 0; nt < 4; ++nt) {
                int m0 = wm * 64 + mt * 16 + g, n0 = wn * 32 + nt * 8 + tq * 2;
                *(float2*)(cb + m0 * CB_LD + n0) = make_float2(c[mt][nt][0], c[mt][nt][1]);
                *(float2*)(cb + (m0 + 8) * CB_LD + n0) = make_float2(c[mt][nt][2], c[mt][nt][3]);
            }
    }
    __syncthreads();
    {
        const float4 bv = *(const float4*)(b1 + J0 + lane * 4);
        #pragma unroll 4
        for (int rr = 0; rr < 16; ++rr) {
            int row = warp * 16 + rr, t = t0 + row;
            if (t < STEPS) {
                float4 v = *(float4*)(cb + row * CB_LD + lane * 4);
                v.x += bv.x; v.y += bv.y; v.z += bv.z; v.w += bv.w;
                *(float4*)(g_hx + ((size_t)b * STEPS + t) * DH + J0 + lane * 4) = v;
            }
        }
    }
}

// ===========================================================================
// Phase B: 128 blocks x 512 threads, 2 batch rows. Feedback GEMM on tensor
// pipe (Wf frags in regs, y ring, x4-unrolled steps -> all ring offsets
// immediate). Layer2: packed f32x2 FMA, W2 pairs pre-packed in smem, h fp32
// duplicated-pair arrays, butterfly reduce, sigmoid on lanes 0-3.
// ===========================================================================
#define YLD 136
// smem byte offsets
#define OFF_YS   139264              // wf: [0,139264)
#define OFF_SHA  141440              // 4608
#define OFF_SHB  146048              // 4608
#define OFF_W2S  150656              // 16*4608 = 73728
#define SMB_TOT  224384

__global__ void __launch_bounds__(512, 1)
narx_recur(const float* __restrict__ W1, const float* __restrict__ W2,
           const float* __restrict__ b2, float* __restrict__ out)
{
    extern __shared__ unsigned char smraw[];
    __half* wf  = (__half*)smraw;
    __half* ys  = (__half*)(smraw + OFF_YS);
    char*   sha = (char*)(smraw + OFF_SHA);
    char*   shb = (char*)(smraw + OFF_SHB);
    char*   w2s = (char*)(smraw + OFF_W2S);

    const int tid = threadIdx.x, warp = tid >> 5, lane = tid & 31;
    const int b0 = blockIdx.x * 2;
    const int jb = warp * 32;
    const int mat = lane >> 3, lrow = lane & 7;
    const int m0 = warp * 2, m1 = m0 + 1;

    // ---- one-time staging ----
    for (int idx = tid; idx < 512 * 64; idx += 512) {
        int j = idx >> 6, q2 = (idx & 63) << 1;
        const float* s = W1 + (size_t)j * DIN + 256 + q2;
        *(__half2*)(wf + j * YLD + q2) = __floats2half2_rn(s[0], s[1]);
    }
    for (int idx = tid; idx < 8 * YLD; idx += 512) ys[idx] = __float2half_rn(0.0f);
    {   // W2 packed pairs (w[m0][j], w[m1][j]), padded layout
        unsigned long long* wp = (unsigned long long*)(w2s + warp * 4608);
        #pragma unroll
        for (int k = 0; k < 16; ++k) {
            int j = lane * 16 + k;
            wp[18 * lane + k] = packf2(W2[(size_t)m0 * DH + j], W2[(size_t)m1 * DH + j]);
        }
    }
    const float bz0 = b2[m0], bz1 = b2[m1];
    __syncthreads();

    // Wf A-fragments resident in registers
    unsigned wfr[2][8][4];
    {
        const unsigned wfb = su32(wf);
        #pragma unroll
        for (int mt = 0; mt < 2; ++mt)
            #pragma unroll
            for (int kt = 0; kt < 8; ++kt) {
                int j = jb + mt * 16 + (mat & 1) * 8 + lrow;
                int q = kt * 16 + (mat >> 1) * 8;
                ldsm4(wfr[mt][kt], wfb + 2u * (unsigned)(j * YLD + q));
            }
    }

    const float* hx0 = g_hx + (size_t)b0 * STEPS * DH;
    const float* hx1 = hx0 + (size_t)STEPS * DH;
    const int m8 = lane >> 2;
    const int ja = jb + m8, jc = jb + 16 + m8;
    const __half* ybase = ys + (lane >> 2) * YLD + (lane & 3) * 2;

    // h store bases (active lanes lane%4==0)
    char* saP = sha + (36 * warp + m8) * 8;
    char* sbP = shb + (36 * warp + m8) * 8;
    // layer2 read bases: per-lane 144B stride
    const char* raP = sha + lane * 144;
    const char* rbP = shb + lane * 144;
    const char* rwP = w2s + warp * 4608 + lane * 144;
    // output pointer (lanes 0-3 only dereference)
    float* optr = out + (size_t)(b0 + (lane & 1)) * STEPS * 32 + m0 + (lane >> 1);
    const int ywi = (lane & 1) * YLD + m0 + (lane >> 1);

    float cur[8];
    cur[0] = __ldcs(hx0 + ja);      cur[1] = __ldcs(hx1 + ja);
    cur[2] = __ldcs(hx0 + ja + 8);  cur[3] = __ldcs(hx1 + ja + 8);
    cur[4] = __ldcs(hx0 + jc);      cur[5] = __ldcs(hx1 + jc);
    cur[6] = __ldcs(hx0 + jc + 8);  cur[7] = __ldcs(hx1 + jc + 8);
    const float* pf0 = hx0 + DH;
    const float* pf1 = hx1 + DH;

    for (int i = 0; i < STEPS; i += 4) {
        #pragma unroll
        for (int u = 0; u < 4; ++u) {
            float c0[4] = {cur[0], cur[1], cur[2], cur[3]};
            float c1[4] = {cur[4], cur[5], cur[6], cur[7]};

            if (i + u + 1 < STEPS) {
                const float* q0 = pf0 + u * DH;
                const float* q1 = pf1 + u * DH;
                cur[0] = __ldcs(q0 + ja);     cur[1] = __ldcs(q1 + ja);
                cur[2] = __ldcs(q0 + ja + 8); cur[3] = __ldcs(q1 + ja + 8);
                cur[4] = __ldcs(q0 + jc);     cur[5] = __ldcs(q1 + jc);
                cur[6] = __ldcs(q0 + jc + 8); cur[7] = __ldcs(q1 + jc + 8);
            }

            // feedback GEMM: slot of block d = (i+u+d)&3 = (u+d)&3 (imm)
            #pragma unroll
            for (int kt = 0; kt < 8; ++kt) {
                const int off = (((u + (kt >> 1)) & 3) << 5) + ((kt & 1) << 4);
                unsigned bb0 = *(const unsigned*)(ybase + off);
                unsigned bb1 = *(const unsigned*)(ybase + off + 8);
                mma16816(c0, wfr[0][kt], bb0, bb1);
                mma16816(c1, wfr[1][kt], bb0, bb1);
            }

            // tanh + duplicated-pair fp32 stores
            if ((lane & 3) == 0) {
                float t0 = tanh_fast(c0[0]), t1 = tanh_fast(c0[1]);
                float t2 = tanh_fast(c0[2]), t3 = tanh_fast(c0[3]);
                float t4 = tanh_fast(c1[0]), t5 = tanh_fast(c1[1]);
                float t6 = tanh_fast(c1[2]), t7 = tanh_fast(c1[3]);
                *(unsigned long long*)(saP)       = packf2(t0, t0);
                *(unsigned long long*)(saP + 64)  = packf2(t2, t2);
                *(unsigned long long*)(saP + 144) = packf2(t4, t4);
                *(unsigned long long*)(saP + 208) = packf2(t6, t6);
                *(unsigned long long*)(sbP)       = packf2(t1, t1);
                *(unsigned long long*)(sbP + 64)  = packf2(t3, t3);
                *(unsigned long long*)(sbP + 144) = packf2(t5, t5);
                *(unsigned long long*)(sbP + 208) = packf2(t7, t7);
            }
            __syncthreads();                     // (A) h ready / ys WAR fence

            // layer 2: packed FMA over 16 j per lane, 2 chains per output pair
            unsigned long long p0 = 0ull, p1 = 0ull, q0a = 0ull, q1a = 0ull;
            #pragma unroll
            for (int t8 = 0; t8 < 8; ++t8) {
                ulonglong2 A = *(const ulonglong2*)(raP + t8 * 16);
                ulonglong2 Bv = *(const ulonglong2*)(rbP + t8 * 16);
                ulonglong2 Wv = *(const ulonglong2*)(rwP + t8 * 16);
                fma2(p0, Wv.x, A.x);  fma2(p1, Wv.y, A.y);
                fma2(q0a, Wv.x, Bv.x); fma2(q1a, Wv.y, Bv.y);
            }
            float2 sP0 = unpk(p0), sP1 = unpk(p1), sQ0 = unpk(q0a), sQ1 = unpk(q1a);
            float a00 = sP0.x + sP1.x, a10 = sP0.y + sP1.y;
            float a01 = sQ0.x + sQ1.x, a11 = sQ0.y + sQ1.y;
            #pragma unroll
            for (int off = 16; off >= 1; off >>= 1) {
                a00 += __shfl_xor_sync(0xffffffffu, a00, off);
                a01 += __shfl_xor_sync(0xffffffffu, a01, off);
                a10 += __shfl_xor_sync(0xffffffffu, a10, off);
                a11 += __shfl_xor_sync(0xffffffffu, a11, off);
            }
            if (lane < 4) {
                float v  = (lane == 0) ? a00 : (lane == 1) ? a01 : (lane == 2) ? a10 : a11;
                float bz = (lane < 2) ? bz0 : bz1;
                float e = __expf(-(v + bz));
                float o = __fdividef(1.0f, 1.0f + e);
                ys[ywi + u * 32] = __float2half_rn(o);
                optr[u * 32] = o;
            }
            __syncthreads();                     // (C) y ready
        }
        pf0 += 4 * DH; pf1 += 4 * DH; optr += 128;
    }
}

extern "C" void kernel_launch(void* const* d_in, const int* in_sizes, int n_in,
                              void* d_out, int out_size)
{
    const float* x  = (const float*)d_in[0];
    const float* W1 = (const float*)d_in[1];
    const float* b1 = (const float*)d_in[2];
    const float* W2 = (const float*)d_in[3];
    const float* b2 = (const float*)d_in[4];
    float* out = (float*)d_out;
    (void)in_sizes; (void)n_in; (void)out_size;

    constexpr size_t smA = XSP * 2 + 128 * WS_LD * 2;   // 78,400 B
    constexpr size_t smB = SMB_TOT;                     // 224,384 B

    cudaFuncSetAttribute(narx_hx, cudaFuncAttributeMaxDynamicSharedMemorySize, (int)smA);
    cudaFuncSetAttribute(narx_recur, cudaFuncAttributeMaxDynamicSharedMemorySize, (int)smB);

    dim3 gA(16, 4, 256);
    narx_hx<<<gA, 256, smA>>>(x, W1, b1);
    narx_recur<<<128, 512, smB>>>(W1, W2, b2, out);
}

// round 15
// speedup vs baseline: 1.8697x; 1.8697x over previous
#include <cuda_runtime.h>
#include <cuda_fp16.h>
#include <cstdint>

#define BATCH 256
#define TSEQ  2048
#define DH    512
#define STEPS 2040
#define DIN   384

__device__ float g_hx[(size_t)BATCH * STEPS * DH];

__device__ __forceinline__ unsigned su32(const void* p) {
    return (unsigned)__cvta_generic_to_shared(p);
}
__device__ __forceinline__ void ldsm4(unsigned* r, unsigned a) {
    asm volatile("ldmatrix.sync.aligned.m8n8.x4.shared.b16 {%0,%1,%2,%3}, [%4];"
                 : "=r"(r[0]), "=r"(r[1]), "=r"(r[2]), "=r"(r[3]) : "r"(a));
}
__device__ __forceinline__ void ldsm2(unsigned& r0, unsigned& r1, unsigned a) {
    asm volatile("ldmatrix.sync.aligned.m8n8.x2.shared.b16 {%0,%1}, [%2];"
                 : "=r"(r0), "=r"(r1) : "r"(a));
}
__device__ __forceinline__ void mma16816(float* c, const unsigned* a, unsigned b0, unsigned b1) {
    asm volatile("mma.sync.aligned.m16n8k16.row.col.f32.f16.f16.f32 "
                 "{%0,%1,%2,%3}, {%4,%5,%6,%7}, {%8,%9}, {%0,%1,%2,%3};"
                 : "+f"(c[0]), "+f"(c[1]), "+f"(c[2]), "+f"(c[3])
                 : "r"(a[0]), "r"(a[1]), "r"(a[2]), "r"(a[3]), "r"(b0), "r"(b1));
}
__device__ __forceinline__ float tanh_fast(float v) {
    float r; asm("tanh.approx.f32 %0, %1;" : "=f"(r) : "f"(v)); return r;
}

// ===========================================================================
// Phase A: Hx = Xwin[128t x 256k] @ W1x^T, fp16 mma  (R9/R12-passing, verbatim)
// ===========================================================================
#define WS_LD 264
#define CB_LD 132
#define XSP   5408

__global__ void __launch_bounds__(256, 2)
narx_hx(const float* __restrict__ x, const float* __restrict__ W1,
        const float* __restrict__ b1)
{
    extern __shared__ unsigned char smraw[];
    __half* xs = (__half*)smraw;
    __half* ws = (__half*)(smraw + XSP * 2);
    float*  cb = (float*)(smraw + XSP * 2);

    const int tid = threadIdx.x, warp = tid >> 5, lane = tid & 31;
    const int wm = warp & 1, wn = warp >> 1;
    const int t0 = blockIdx.x * 128, J0 = blockIdx.y * 128, b = blockIdx.z;

    {
        const float* xb = x + (size_t)b * (TSEQ * 32) + (size_t)t0 * 32;
        const int lim = TSEQ * 32 - t0 * 32;
        for (int i = tid; i < 4320; i += 256) {
            float v = (i < lim) ? xb[i] : 0.0f;
            xs[(i >> 5) * 40 + (i & 31)] = __float2half_rn(v);
        }
    }
    for (int idx = tid; idx < 128 * 128; idx += 256) {
        int j = idx >> 7, k2 = (idx & 127) << 1;
        const float* w = W1 + (size_t)(J0 + j) * DIN + k2;
        *(__half2*)(ws + j * WS_LD + k2) = __floats2half2_rn(w[0], w[1]);
    }
    __syncthreads();

    float c[4][4][4];
    #pragma unroll
    for (int i = 0; i < 4; i++)
        #pragma unroll
        for (int j = 0; j < 4; j++)
            #pragma unroll
            for (int r = 0; r < 4; r++) c[i][j][r] = 0.0f;

    const unsigned xsb = su32(xs), wsb = su32(ws);
    const int mat = lane >> 3, lrow = lane & 7;

    #pragma unroll 4
    for (int ks = 0; ks < 16; ++ks) {
        unsigned a[4][4], b0[4], b1[4];
        const int col = ks * 16 + (mat >> 1) * 8;
        const int ce  = (col >> 5) * 40 + (col & 31);
        #pragma unroll
        for (int mt = 0; mt < 4; ++mt) {
            int row = wm * 64 + mt * 16 + (mat & 1) * 8 + lrow;
            ldsm4(a[mt], xsb + 2u * (unsigned)(row * 40 + ce));
        }
        const int bcol = ks * 16 + ((lane >> 3) & 1) * 8;
        #pragma unroll
        for (int nt = 0; nt < 4; ++nt) {
            int br = wn * 32 + nt * 8 + lrow;
            ldsm2(b0[nt], b1[nt], wsb + 2u * (unsigned)(br * WS_LD + bcol));
        }
        #pragma unroll
        for (int mt = 0; mt < 4; ++mt)
            #pragma unroll
            for (int nt = 0; nt < 4; ++nt)
                mma16816(c[mt][nt], a[mt], b0[nt], b1[nt]);
    }

    __syncthreads();
    {
        const int g = lane >> 2, tq = lane & 3;
        #pragma unroll
        for (int mt = 0; mt < 4; ++mt)
            #pragma unroll
            for (int nt = 0; nt < 4; ++nt) {
                int m0 = wm * 64 + mt * 16 + g, n0 = wn * 32 + nt * 8 + tq * 2;
                *(float2*)(cb + m0 * CB_LD + n0) = make_float2(c[mt][nt][0], c[mt][nt][1]);
                *(float2*)(cb + (m0 + 8) * CB_LD + n0) = make_float2(c[mt][nt][2], c[mt][nt][3]);
            }
    }
    __syncthreads();
    {
        const float4 bv = *(const float4*)(b1 + J0 + lane * 4);
        #pragma unroll 4
        for (int rr = 0; rr < 16; ++rr) {
            int row = warp * 16 + rr, t = t0 + row;
            if (t < STEPS) {
                float4 v = *(float4*)(cb + row * CB_LD + lane * 4);
                v.x += bv.x; v.y += bv.y; v.z += bv.z; v.w += bv.w;
                *(float4*)(g_hx + ((size_t)b * STEPS + t) * DH + J0 + lane * 4) = v;
            }
        }
    }
}

// ===========================================================================
// Phase B: 128 blocks x 512 threads, 2 batch rows. BOTH layers on tensor pipe.
// Feedback: Wf A-frags in regs, ys fp16 ring [8n][136]. Layer2: h stored fp16
// to harr[8n][520] once, W2 A-frags in regs (staged via dead wf area), per-warp
// k-chunk HMMA -> 64-float partials -> 16-way reduce by 64 threads -> sigmoid.
// ===========================================================================
#define YLD 136
#define HLD 520
// smem byte offsets
#define OFF_YS   139264              // wf staging: [0,139264) (dead after init)
#define OFF_HARR 141440              // 8*520*2 = 8320
#define OFF_PBUF 149760              // 16*64*4 = 4096
#define OFF_SB2  153856              // 64*4 = 256
#define SMB_TOT  154112

__global__ void __launch_bounds__(512, 1)
narx_recur(const float* __restrict__ W1, const float* __restrict__ W2,
           const float* __restrict__ b2, float* __restrict__ out)
{
    extern __shared__ unsigned char smraw[];
    __half* wf   = (__half*)smraw;                   // staging (wf, then W2)
    __half* ys   = (__half*)(smraw + OFF_YS);
    __half* harr = (__half*)(smraw + OFF_HARR);
    float*  pbuf = (float*)(smraw + OFF_PBUF);
    float*  sb2  = (float*)(smraw + OFF_SB2);

    const int tid = threadIdx.x, warp = tid >> 5, lane = tid & 31;
    const int b0 = blockIdx.x * 2;
    const int jb = warp * 32;
    const int mat = lane >> 3, lrow = lane & 7;

    // ---- stage Wf = W1[:,256:384] fp16, zero ys + harr ----
    for (int idx = tid; idx < 512 * 64; idx += 512) {
        int j = idx >> 6, q2 = (idx & 63) << 1;
        const float* s = W1 + (size_t)j * DIN + 256 + q2;
        *(__half2*)(wf + j * YLD + q2) = __floats2half2_rn(s[0], s[1]);
    }
    for (int idx = tid; idx < 8 * YLD; idx += 512) ys[idx] = __float2half_rn(0.0f);
    for (int idx = tid; idx < 8 * HLD; idx += 512) harr[idx] = __float2half_rn(0.0f);
    if (tid < 64) sb2[tid] = b2[tid >> 1];
    __syncthreads();

    // Wf A-fragments resident in registers (2 mt x 8 kt x 4)
    unsigned wfr[2][8][4];
    {
        const unsigned wfb = su32(wf);
        #pragma unroll
        for (int mt = 0; mt < 2; ++mt)
            #pragma unroll
            for (int kt = 0; kt < 8; ++kt) {
                int j = jb + mt * 16 + (mat & 1) * 8 + lrow;
                int q = kt * 16 + (mat >> 1) * 8;
                ldsm4(wfr[mt][kt], wfb + 2u * (unsigned)(j * YLD + q));
            }
    }
    __syncthreads();                 // all ldsm done before wf area is reused

    // ---- stage W2 [32 m][520] fp16 into (dead) wf area; load A-frags ----
    {
        __half* w2h = wf;
        for (int idx = tid; idx < 32 * 256; idx += 512) {
            int m = idx >> 8, j2 = (idx & 255) << 1;
            const float* s = W2 + (size_t)m * DH + j2;
            *(__half2*)(w2h + m * HLD + j2) = __floats2half2_rn(s[0], s[1]);
        }
    }
    __syncthreads();
    unsigned w2f[2][2][4];           // [mt][kt][reg]: warp's k-chunk = [32w,32w+32)
    {
        const unsigned w2b = su32(wf);
        #pragma unroll
        for (int mt = 0; mt < 2; ++mt)
            #pragma unroll
            for (int kt = 0; kt < 2; ++kt) {
                int m = mt * 16 + (mat & 1) * 8 + lrow;
                int k = jb + kt * 16 + (mat >> 1) * 8;
                ldsm4(w2f[mt][kt], w2b + 2u * (unsigned)(m * HLD + k));
            }
    }
    __syncthreads();

    const float* hx0 = g_hx + (size_t)b0 * STEPS * DH;
    const float* hx1 = hx0 + (size_t)STEPS * DH;
    const int m8 = lane >> 2;
    const int ja = jb + m8, jc = jb + 16 + m8;
    const __half* ybase = ys + (lane >> 2) * YLD + (lane & 3) * 2;
    // layer-2 B-frag address (row = lrow, col base = jb + ((lane>>3)&1)*8)
    const unsigned lsAddr = su32(harr) + 2u * (unsigned)(lrow * HLD + jb + ((lane >> 3) & 1) * 8);
    float* pw = pbuf + warp * 64;
    float* optr = out + (size_t)(b0 + (tid & 1)) * STEPS * 32 + (tid >> 1);
    const int ywi = (tid & 1) * YLD + (tid >> 1);

    float cur[8];
    cur[0] = __ldcs(hx0 + ja);      cur[1] = __ldcs(hx1 + ja);
    cur[2] = __ldcs(hx0 + ja + 8);  cur[3] = __ldcs(hx1 + ja + 8);
    cur[4] = __ldcs(hx0 + jc);      cur[5] = __ldcs(hx1 + jc);
    cur[6] = __ldcs(hx0 + jc + 8);  cur[7] = __ldcs(hx1 + jc + 8);
    const float* pf0 = hx0 + DH;
    const float* pf1 = hx1 + DH;

    for (int i = 0; i < STEPS; i += 4) {
        #pragma unroll
        for (int u = 0; u < 4; ++u) {
            float c0[4] = {cur[0], cur[1], cur[2], cur[3]};
            float c1[4] = {cur[4], cur[5], cur[6], cur[7]};

            if (i + u + 1 < STEPS) {
                const float* q0 = pf0 + u * DH;
                const float* q1 = pf1 + u * DH;
                cur[0] = __ldcs(q0 + ja);     cur[1] = __ldcs(q1 + ja);
                cur[2] = __ldcs(q0 + ja + 8); cur[3] = __ldcs(q1 + ja + 8);
                cur[4] = __ldcs(q0 + jc);     cur[5] = __ldcs(q1 + jc);
                cur[6] = __ldcs(q0 + jc + 8); cur[7] = __ldcs(q1 + jc + 8);
            }

            // feedback GEMM: slot of block d = (u+d)&3 (compile-time imm)
            #pragma unroll
            for (int kt = 0; kt < 8; ++kt) {
                const int off = (((u + (kt >> 1)) & 3) << 5) + ((kt & 1) << 4);
                unsigned bb0 = *(const unsigned*)(ybase + off);
                unsigned bb1 = *(const unsigned*)(ybase + off + 8);
                mma16816(c0, wfr[0][kt], bb0, bb1);
                mma16816(c1, wfr[1][kt], bb0, bb1);
            }

            // tanh -> fp16 h into harr[n][j] (rows 0,1; rows 2-7 stay zero)
            if ((lane & 3) == 0) {
                harr[ja]            = __float2half_rn(tanh_fast(c0[0]));
                harr[HLD + ja]      = __float2half_rn(tanh_fast(c0[1]));
                harr[ja + 8]        = __float2half_rn(tanh_fast(c0[2]));
                harr[HLD + ja + 8]  = __float2half_rn(tanh_fast(c0[3]));
                harr[jc]            = __float2half_rn(tanh_fast(c1[0]));
                harr[HLD + jc]      = __float2half_rn(tanh_fast(c1[1]));
                harr[jc + 8]        = __float2half_rn(tanh_fast(c1[2]));
                harr[HLD + jc + 8]  = __float2half_rn(tanh_fast(c1[3]));
            }
            __syncthreads();                     // (A) h ready

            // layer-2 GEMM on tensor pipe: warp's k-chunk, D partial [32m x 2n]
            float d0[4] = {0.f, 0.f, 0.f, 0.f};
            float d1[4] = {0.f, 0.f, 0.f, 0.f};
            #pragma unroll
            for (int kt = 0; kt < 2; ++kt) {
                unsigned bb0, bb1;
                ldsm2(bb0, bb1, lsAddr + kt * 32u);
                mma16816(d0, w2f[0][kt], bb0, bb1);
                mma16816(d1, w2f[1][kt], bb0, bb1);
            }
            if ((lane & 3) == 0) {
                *(float2*)(pw + 2 * m8)        = make_float2(d0[0], d0[1]);
                *(float2*)(pw + 2 * (m8 + 8))  = make_float2(d0[2], d0[3]);
                *(float2*)(pw + 2 * (m8 + 16)) = make_float2(d1[0], d1[1]);
                *(float2*)(pw + 2 * (m8 + 24)) = make_float2(d1[2], d1[3]);
            }
            __syncthreads();                     // (B) partials ready

            // reduce 16 partials + sigmoid + feedback + output (64 threads)
            if (tid < 64) {
                float z = sb2[tid];
                #pragma unroll
                for (int w = 0; w < 16; ++w) z += pbuf[w * 64 + tid];
                float o = __fdividef(1.0f, 1.0f + __expf(-z));
                ys[ywi + u * 32] = __float2half_rn(o);   // new-y slot = u
                optr[u * 32] = o;
            }
            __syncthreads();                     // (C) y ready
        }
        pf0 += 4 * DH; pf1 += 4 * DH; optr += 128;
    }
}

extern "C" void kernel_launch(void* const* d_in, const int* in_sizes, int n_in,
                              void* d_out, int out_size)
{
    const float* x  = (const float*)d_in[0];
    const float* W1 = (const float*)d_in[1];
    const float* b1 = (const float*)d_in[2];
    const float* W2 = (const float*)d_in[3];
    const float* b2 = (const float*)d_in[4];
    float* out = (float*)d_out;
    (void)in_sizes; (void)n_in; (void)out_size;

    constexpr size_t smA = XSP * 2 + 128 * WS_LD * 2;   // 78,400 B
    constexpr size_t smB = SMB_TOT;                     // 154,112 B

    cudaFuncSetAttribute(narx_hx, cudaFuncAttributeMaxDynamicSharedMemorySize, (int)smA);
    cudaFuncSetAttribute(narx_recur, cudaFuncAttributeMaxDynamicSharedMemorySize, (int)smB);

    dim3 gA(16, 4, 256);
    narx_hx<<<gA, 256, smA>>>(x, W1, b1);
    narx_recur<<<128, 512, smB>>>(W1, W2, b2, out);
}